// round 1
// baseline (speedup 1.0000x reference)
#include <cuda_runtime.h>
#include <cstdint>
#include <cstdio>

#define B_  128
#define S_  50
#define T_  32
#define TQ_ 32
#define H_  256
#define V_  50257
#define G3  768

// ---------------- scratch (device globals; no allocation) ----------------
__device__ float g_ctx [B_*S_*H_];
__device__ float g_qemb[B_*TQ_*H_];
__device__ float g_gif [B_*S_*G3];
__device__ float g_gib [B_*S_*G3];
__device__ float g_giq [B_*TQ_*G3];
__device__ float g_outf[B_*S_*H_];
__device__ float g_outb[B_*S_*H_];
__device__ float g_q   [B_*H_];
__device__ float g_af  [B_*H_];

// ---------------- helpers ----------------
__device__ __forceinline__ float sigmoidf_(float x){ return 1.0f/(1.0f+expf(-x)); }

__device__ __forceinline__ unsigned smem_u32_(const void* p){
    unsigned r;
    asm("{ .reg .u64 t; cvta.to.shared.u64 t, %1; cvt.u32.u64 %0, t; }" : "=r"(r) : "l"(p));
    return r;
}
__device__ __forceinline__ void st_cluster_f32_(unsigned laddr, unsigned rank, float v){
    unsigned r;
    asm volatile("mapa.shared::cluster.u32 %0, %1, %2;" : "=r"(r) : "r"(laddr), "r"(rank));
    asm volatile("st.shared::cluster.f32 [%0], %1;" :: "r"(r), "f"(v) : "memory");
}
__device__ __forceinline__ void cluster_sync_(){
    asm volatile("barrier.cluster.arrive.aligned;" ::: "memory");
    asm volatile("barrier.cluster.wait.aligned;" ::: "memory");
}
__device__ __forceinline__ unsigned ctarank_(){
    unsigned r; asm("mov.u32 %0, %%cluster_ctarank;" : "=r"(r)); return r;
}

// ---------------- 1) embedding + position encoding ----------------
// ctx[b,s,h] = sum_t emb[contexts[b,s,t],h] * (1 - t/31 - (h/255)*(1 - 2t/31))
__global__ void embed_pe_kernel(const int* __restrict__ ctx, const float* __restrict__ emb){
    int bs = blockIdx.x;          // b*S_ + s
    int h  = threadIdx.x;         // 0..255
    __shared__ int ids[T_];
    if (h < T_) ids[h] = ctx[bs*T_ + h];
    __syncthreads();
    float e = (float)h * (1.0f/255.0f);
    float acc = 0.f;
#pragma unroll
    for (int t = 0; t < T_; t++){
        float s = (float)t * (1.0f/31.0f);
        float l = 1.0f - s - e*(1.0f - 2.0f*s);
        acc += emb[(size_t)ids[t]*H_ + h] * l;
    }
    g_ctx[(size_t)bs*H_ + h] = acc;
}

__global__ void qemb_kernel(const int* __restrict__ q, const float* __restrict__ emb){
    int i = blockIdx.x;           // b*TQ_ + t
    int h = threadIdx.x;
    g_qemb[(size_t)i*H_ + h] = emb[(size_t)q[i]*H_ + h];
}

// ---------------- 2) GEMM: C[m,n] = sum_k A[m,k] * W[n,k] + bias[n], K=256 ----------------
__global__ __launch_bounds__(256) void gemm_atb(const float* __restrict__ A,
                                                const float* __restrict__ W,
                                                const float* __restrict__ bias,
                                                float* __restrict__ C, int N)
{
    __shared__ float As[32][132];
    __shared__ float Bs[32][68];
    int tid = threadIdx.x;
    int bm = blockIdx.x * 128;
    int bn = blockIdx.y * 64;
    int tx = tid & 15, ty = tid >> 4;

    float acc[8][4];
#pragma unroll
    for (int i = 0; i < 8; i++)
#pragma unroll
        for (int j = 0; j < 4; j++) acc[i][j] = 0.f;

    for (int k0 = 0; k0 < 256; k0 += 32){
#pragma unroll
        for (int i = 0; i < 4; i++){
            int lin = tid + i*256;
            int row = lin >> 3, kk = (lin & 7) << 2;
            float4 v = *(const float4*)(A + (size_t)(bm+row)*256 + k0 + kk);
            As[kk  ][row] = v.x; As[kk+1][row] = v.y;
            As[kk+2][row] = v.z; As[kk+3][row] = v.w;
        }
#pragma unroll
        for (int i = 0; i < 2; i++){
            int lin = tid + i*256;
            int row = lin >> 3, kk = (lin & 7) << 2;
            int n = bn + row;
            float4 v = make_float4(0.f,0.f,0.f,0.f);
            if (n < N) v = *(const float4*)(W + (size_t)n*256 + k0 + kk);
            Bs[kk  ][row] = v.x; Bs[kk+1][row] = v.y;
            Bs[kk+2][row] = v.z; Bs[kk+3][row] = v.w;
        }
        __syncthreads();
#pragma unroll
        for (int k = 0; k < 32; k++){
            float a[8], b[4];
#pragma unroll
            for (int i = 0; i < 8; i++) a[i] = As[k][ty*8 + i];
#pragma unroll
            for (int j = 0; j < 4; j++) b[j] = Bs[k][tx*4 + j];
#pragma unroll
            for (int i = 0; i < 8; i++)
#pragma unroll
                for (int j = 0; j < 4; j++) acc[i][j] += a[i]*b[j];
        }
        __syncthreads();
    }
#pragma unroll
    for (int i = 0; i < 8; i++){
        int m = bm + ty*8 + i;
#pragma unroll
        for (int j = 0; j < 4; j++){
            int n = bn + tx*4 + j;
            if (n < N) C[(size_t)m*N + n] = acc[i][j] + bias[n];
        }
    }
}

// ---------------- 3) GRU recurrences: cluster-resident Whh ----------------
// Cluster of 4 CTAs. Each CTA owns 64 hidden units j (192 Whh rows in smem).
// 33 clusters: chains f (cid 0..10), b (11..21), q (22..32); 12 batch per cluster.
// Per step: local 192x256 matvec over batch group; h broadcast via DSMEM; 1 cluster barrier.
#define GRU_SMEM_FLOATS (3*64*257 + 2*12*256 + 192)
#define GRU_SMEM_BYTES  (GRU_SMEM_FLOATS*4)

__global__ void __cluster_dims__(4,1,1) __launch_bounds__(256,1)
gru_kernel(const float* __restrict__ Whh_f, const float* __restrict__ Whh_b, const float* __restrict__ Whh_q,
           const float* __restrict__ bhh_f, const float* __restrict__ bhh_b, const float* __restrict__ bhh_q)
{
    extern __shared__ float sm[];
    float* Whs  = sm;                     // [3*64][257]
    float* hbuf = sm + 3*64*257;          // [2][12][256]
    float* bhs  = hbuf + 2*12*256;        // [192]

    int tid = threadIdx.x;
    unsigned rank = ctarank_();
    int cid   = blockIdx.x >> 2;
    int chain = cid / 11;                 // 0=f, 1=b, 2=q
    int b0    = (cid % 11) * 12;

    const float *Whh, *bhh, *gi;
    float* outp;
    int steps;
    if (chain == 0){ Whh = Whh_f; bhh = bhh_f; gi = g_gif; outp = g_outf; steps = S_;  }
    else if (chain == 1){ Whh = Whh_b; bhh = bhh_b; gi = g_gib; outp = g_outb; steps = S_;  }
    else { Whh = Whh_q; bhh = bhh_q; gi = g_giq; outp = g_q;    steps = TQ_; }

    // load this CTA's Whh slice: rows {g*256 + rank*64 + jj} for g=0..2, jj=0..63
    {
        int k = tid;  // 0..255 -> coalesced along k
#pragma unroll 4
        for (int rr = 0; rr < 192; rr++){
            int g = rr >> 6, jj = rr & 63;
            Whs[rr*257 + k] = Whh[((size_t)(g*256 + (int)rank*64 + jj))*256 + k];
        }
        if (tid < 192){
            int g = tid >> 6, jj = tid & 63;
            bhs[tid] = bhh[g*256 + (int)rank*64 + jj];
        }
        for (int i = tid; i < 2*12*256; i += 256) hbuf[i] = 0.f;
    }
    cluster_sync_();

    int j  = tid & 63;
    int bg = tid >> 6;                    // 0..3, each handles 3 batch
    int jglob = (int)rank*64 + j;
    float br = bhs[j], bz = bhs[64 + j], bn = bhs[128 + j];
    const float* wr = &Whs[ j        *257];
    const float* wz = &Whs[(64  + j) *257];
    const float* wn = &Whs[(128 + j) *257];
    unsigned hbuf_base = smem_u32_(hbuf);

    for (int step = 0; step < steps; step++){
        int cur = step & 1, nxt = cur ^ 1;
        int pos = (chain == 1) ? (S_ - 1 - step) : step;
        const float* h0 = hbuf + cur*3072 + (bg*3 + 0)*256;
        const float* h1 = h0 + 256;
        const float* h2 = h0 + 512;

        float ar0=0,ar1=0,ar2=0, az0=0,az1=0,az2=0, an0=0,an1=0,an2=0;
#pragma unroll 4
        for (int k = 0; k < 256; k++){
            float r_ = wr[k], z_ = wz[k], n_ = wn[k];
            float x0 = h0[k], x1 = h1[k], x2 = h2[k];
            ar0 += r_*x0; ar1 += r_*x1; ar2 += r_*x2;
            az0 += z_*x0; az1 += z_*x1; az2 += z_*x2;
            an0 += n_*x0; an1 += n_*x1; an2 += n_*x2;
        }
        float arr[3] = {ar0,ar1,ar2}, azz[3] = {az0,az1,az2}, ann[3] = {an0,an1,an2};
#pragma unroll
        for (int i = 0; i < 3; i++){
            int bl = bg*3 + i;
            int bglob = b0 + bl;
            float gr = 0.f, gz = 0.f, gn = 0.f;
            if (bglob < B_){
                const float* gir = gi + ((size_t)bglob*steps + pos)*G3;
                gr = gir[jglob]; gz = gir[256 + jglob]; gn = gir[512 + jglob];
            }
            float hp = hbuf[cur*3072 + bl*256 + jglob];
            float rg = sigmoidf_(gr + arr[i] + br);
            float zg = sigmoidf_(gz + azz[i] + bz);
            float ng = tanhf(gn + rg*(ann[i] + bn));
            float hv = (1.f - zg)*ng + zg*hp;
            if (bglob < B_){
                if (chain == 2){ if (step == steps - 1) outp[(size_t)bglob*H_ + jglob] = hv; }
                else outp[((size_t)bglob*S_ + pos)*H_ + jglob] = hv;
            }
            unsigned la = hbuf_base + (unsigned)((nxt*3072 + bl*256 + jglob)*4);
            st_cluster_f32_(la, 0, hv);
            st_cluster_f32_(la, 1, hv);
            st_cluster_f32_(la, 2, hv);
            st_cluster_f32_(la, 3, hv);
        }
        cluster_sync_();   // release DSMEM writes; all CTAs move to next step together
    }
}

// ---------------- 4) attention + read + tanh(q*read) ----------------
__global__ void attn_kernel(){
    int b = blockIdx.x, h = threadIdx.x;
    __shared__ float en[S_];
    __shared__ float red[8];
    float qh = g_q[(size_t)b*H_ + h];
    int lane = h & 31, wid = h >> 5;
    for (int s = 0; s < S_; s++){
        float f = g_outf[((size_t)b*S_ + s)*H_ + h] + g_outb[((size_t)b*S_ + s)*H_ + h];
        float p = f * qh;
#pragma unroll
        for (int o = 16; o; o >>= 1) p += __shfl_xor_sync(0xffffffffu, p, o);
        if (lane == 0) red[wid] = p;
        __syncthreads();
        if (h < 8){
            float t = red[h];
            t += __shfl_xor_sync(0xffu, t, 4);
            t += __shfl_xor_sync(0xffu, t, 2);
            t += __shfl_xor_sync(0xffu, t, 1);
            if (h == 0) en[s] = t;
        }
        __syncthreads();
    }
    float mx = -1e30f;
    for (int s = 0; s < S_; s++) mx = fmaxf(mx, en[s]);
    float sum = 0.f;
    for (int s = 0; s < S_; s++) sum += expf(en[s] - mx);
    float inv = 1.f / sum;
    float rd = 0.f;
    for (int s = 0; s < S_; s++){
        float a = expf(en[s] - mx) * inv;
        rd += a * (g_outf[((size_t)b*S_ + s)*H_ + h] + g_outb[((size_t)b*S_ + s)*H_ + h]);
    }
    g_af[(size_t)b*H_ + h] = tanhf(qh * rd);
}

// ---------------- launch ----------------
extern "C" void kernel_launch(void* const* d_in, const int* in_sizes, int n_in,
                              void* d_out, int out_size)
{
    const int*   contexts  = (const int*)  d_in[0];
    const int*   questions = (const int*)  d_in[1];
    const float* emb       = (const float*)d_in[2];
    const float* Wih_f     = (const float*)d_in[3];
    const float* Whh_f     = (const float*)d_in[4];
    const float* bih_f     = (const float*)d_in[5];
    const float* bhh_f     = (const float*)d_in[6];
    const float* Wih_b     = (const float*)d_in[7];
    const float* Whh_b     = (const float*)d_in[8];
    const float* bih_b     = (const float*)d_in[9];
    const float* bhh_b     = (const float*)d_in[10];
    const float* Wih_q     = (const float*)d_in[11];
    const float* Whh_q     = (const float*)d_in[12];
    const float* bih_q     = (const float*)d_in[13];
    const float* bhh_q     = (const float*)d_in[14];
    const float* Wo        = (const float*)d_in[15];
    const float* bo        = (const float*)d_in[16];
    float* out = (float*)d_out;

    float *p_ctx, *p_qemb, *p_gif, *p_gib, *p_giq, *p_af;
    cudaGetSymbolAddress((void**)&p_ctx,  g_ctx);
    cudaGetSymbolAddress((void**)&p_qemb, g_qemb);
    cudaGetSymbolAddress((void**)&p_gif,  g_gif);
    cudaGetSymbolAddress((void**)&p_gib,  g_gib);
    cudaGetSymbolAddress((void**)&p_giq,  g_giq);
    cudaGetSymbolAddress((void**)&p_af,   g_af);

    cudaFuncSetAttribute(gru_kernel, cudaFuncAttributeMaxDynamicSharedMemorySize, GRU_SMEM_BYTES);

    // 1) embeddings
    embed_pe_kernel<<<B_*S_, 256>>>(contexts, emb);
    qemb_kernel<<<B_*TQ_, 256>>>(questions, emb);

    // 2) input-gate GEMMs (bias = bih folded in)
    gemm_atb<<<dim3(B_*S_/128, G3/64), 256>>>(p_ctx,  Wih_f, bih_f, p_gif, G3);
    gemm_atb<<<dim3(B_*S_/128, G3/64), 256>>>(p_ctx,  Wih_b, bih_b, p_gib, G3);
    gemm_atb<<<dim3(B_*TQ_/128, G3/64), 256>>>(p_qemb, Wih_q, bih_q, p_giq, G3);

    // 3) all three GRU chains concurrently (33 clusters x 4 CTAs)
    gru_kernel<<<132, 256, GRU_SMEM_BYTES>>>(Whh_f, Whh_b, Whh_q, bhh_f, bhh_b, bhh_q);

    // 4) attention + read + tanh
    attn_kernel<<<B_, 256>>>();

    // 5) vocab projection: out = af @ Wo^T + bo
    gemm_atb<<<dim3(1, (V_ + 63)/64), 256>>>(p_af, Wo, bo, out, V_);
}

// round 2
// speedup vs baseline: 1.0129x; 1.0129x over previous
#include <cuda_runtime.h>
#include <cstdint>
#include <cstdio>

#define B_  128
#define S_  50
#define T_  32
#define TQ_ 32
#define H_  256
#define V_  50257
#define G3  768

typedef unsigned long long ull;

// ---------------- scratch (device globals; no allocation) ----------------
__device__ float g_ctx [B_*S_*H_];
__device__ float g_qemb[B_*TQ_*H_];
__device__ float g_gif [B_*S_*G3];
__device__ float g_gib [B_*S_*G3];
__device__ float g_giq [B_*TQ_*G3];
__device__ float g_outf[B_*S_*H_];
__device__ float g_outb[B_*S_*H_];
__device__ float g_q   [B_*H_];
__device__ float g_af  [B_*H_];

// ---------------- helpers ----------------
__device__ __forceinline__ float sigmoidf_(float x){ return 1.0f/(1.0f+expf(-x)); }

__device__ __forceinline__ ull pack2_(float lo, float hi){
    ull r; asm("mov.b64 %0, {%1, %2};" : "=l"(r) : "f"(lo), "f"(hi)); return r;
}
__device__ __forceinline__ ull dup2_(float v){
    ull r; asm("mov.b64 %0, {%1, %1};" : "=l"(r) : "f"(v)); return r;
}
__device__ __forceinline__ void fma2_(ull& d, ull a, ull b){
    asm("fma.rn.f32x2 %0, %1, %2, %0;" : "+l"(d) : "l"(a), "l"(b));
}
__device__ __forceinline__ float2 unpack2_(ull v){
    float2 r; asm("mov.b64 {%0, %1}, %2;" : "=f"(r.x), "=f"(r.y) : "l"(v)); return r;
}
__device__ __forceinline__ unsigned smem_u32_(const void* p){
    unsigned r;
    asm("{ .reg .u64 t; cvta.to.shared.u64 t, %1; cvt.u32.u64 %0, t; }" : "=r"(r) : "l"(p));
    return r;
}
__device__ __forceinline__ void st_cluster_f32_(unsigned laddr, unsigned rank, float v){
    unsigned r;
    asm volatile("mapa.shared::cluster.u32 %0, %1, %2;" : "=r"(r) : "r"(laddr), "r"(rank));
    asm volatile("st.shared::cluster.f32 [%0], %1;" :: "r"(r), "f"(v) : "memory");
}
__device__ __forceinline__ void cluster_sync_(){
    asm volatile("barrier.cluster.arrive.aligned;" ::: "memory");
    asm volatile("barrier.cluster.wait.aligned;" ::: "memory");
}
__device__ __forceinline__ unsigned ctarank_(){
    unsigned r; asm("mov.u32 %0, %%cluster_ctarank;" : "=r"(r)); return r;
}

// ---------------- 1) embedding + position encoding ----------------
__global__ void embed_pe_kernel(const int* __restrict__ ctx, const float* __restrict__ emb){
    int bs = blockIdx.x;          // b*S_ + s
    int h  = threadIdx.x;         // 0..255
    __shared__ int ids[T_];
    if (h < T_) ids[h] = ctx[bs*T_ + h];
    __syncthreads();
    float e = (float)h * (1.0f/255.0f);
    float acc = 0.f;
#pragma unroll
    for (int t = 0; t < T_; t++){
        float s = (float)t * (1.0f/31.0f);
        float l = 1.0f - s - e*(1.0f - 2.0f*s);
        acc += emb[(size_t)ids[t]*H_ + h] * l;
    }
    g_ctx[(size_t)bs*H_ + h] = acc;
}

__global__ void qemb_kernel(const int* __restrict__ q, const float* __restrict__ emb){
    int i = blockIdx.x;           // b*TQ_ + t
    int h = threadIdx.x;
    g_qemb[(size_t)i*H_ + h] = emb[(size_t)q[i]*H_ + h];
}

// ---------------- 2) GEMM core with packed f32x2 FMAs ----------------
// C[m,n] = sum_k A[m,k] * W[n,k] + bias[n]; K = 256. Tile 128(m) x 64(n).
__device__ __forceinline__ void gemm_body(const float* __restrict__ A,
                                          const float* __restrict__ W,
                                          const float* __restrict__ bias,
                                          float* __restrict__ C,
                                          int N, int bm, int bn)
{
    __shared__ float As[32][132];
    __shared__ float Bs[32][68];
    int tid = threadIdx.x;
    int tx = tid & 15, ty = tid >> 4;

    ull acc[4][4];
#pragma unroll
    for (int i = 0; i < 4; i++)
#pragma unroll
        for (int j = 0; j < 4; j++) acc[i][j] = 0ull;

    for (int k0 = 0; k0 < 256; k0 += 32){
#pragma unroll
        for (int i = 0; i < 4; i++){
            int lin = tid + i*256;
            int row = lin >> 3, kk = (lin & 7) << 2;
            float4 v = *(const float4*)(A + (size_t)(bm+row)*256 + k0 + kk);
            As[kk  ][row] = v.x; As[kk+1][row] = v.y;
            As[kk+2][row] = v.z; As[kk+3][row] = v.w;
        }
#pragma unroll
        for (int i = 0; i < 2; i++){
            int lin = tid + i*256;
            int row = lin >> 3, kk = (lin & 7) << 2;
            int n = bn + row;
            float4 v = make_float4(0.f,0.f,0.f,0.f);
            if (n < N) v = *(const float4*)(W + (size_t)n*256 + k0 + kk);
            Bs[kk  ][row] = v.x; Bs[kk+1][row] = v.y;
            Bs[kk+2][row] = v.z; Bs[kk+3][row] = v.w;
        }
        __syncthreads();
#pragma unroll
        for (int k = 0; k < 32; k++){
            float4 a0 = *(const float4*)(&As[k][ty*8]);
            float4 a1 = *(const float4*)(&As[k][ty*8+4]);
            float4 bv = *(const float4*)(&Bs[k][tx*4]);
            ull ap0 = pack2_(a0.x, a0.y);
            ull ap1 = pack2_(a0.z, a0.w);
            ull ap2 = pack2_(a1.x, a1.y);
            ull ap3 = pack2_(a1.z, a1.w);
            ull bd0 = dup2_(bv.x), bd1 = dup2_(bv.y), bd2 = dup2_(bv.z), bd3 = dup2_(bv.w);
            fma2_(acc[0][0], ap0, bd0); fma2_(acc[0][1], ap0, bd1);
            fma2_(acc[0][2], ap0, bd2); fma2_(acc[0][3], ap0, bd3);
            fma2_(acc[1][0], ap1, bd0); fma2_(acc[1][1], ap1, bd1);
            fma2_(acc[1][2], ap1, bd2); fma2_(acc[1][3], ap1, bd3);
            fma2_(acc[2][0], ap2, bd0); fma2_(acc[2][1], ap2, bd1);
            fma2_(acc[2][2], ap2, bd2); fma2_(acc[2][3], ap2, bd3);
            fma2_(acc[3][0], ap3, bd0); fma2_(acc[3][1], ap3, bd1);
            fma2_(acc[3][2], ap3, bd2); fma2_(acc[3][3], ap3, bd3);
        }
        __syncthreads();
    }
#pragma unroll
    for (int ip = 0; ip < 4; ip++){
        int m = bm + ty*8 + ip*2;
#pragma unroll
        for (int j = 0; j < 4; j++){
            int n = bn + tx*4 + j;
            if (n < N){
                float2 v = unpack2_(acc[ip][j]);
                float bb = bias[n];
                C[(size_t)m*N + n]       = v.x + bb;
                C[(size_t)(m+1)*N + n]   = v.y + bb;
            }
        }
    }
}

// Fused kernel for the three input-gate GEMMs (z selects the problem)
__global__ __launch_bounds__(256) void gemm3_kernel(
    const float* A0, const float* W0, const float* c0, float* C0, int M0,
    const float* A1, const float* W1, const float* c1, float* C1, int M1,
    const float* A2, const float* W2, const float* c2, float* C2, int M2)
{
    const float *A, *W, *cb; float* C; int M;
    if (blockIdx.z == 0){ A=A0; W=W0; cb=c0; C=C0; M=M0; }
    else if (blockIdx.z == 1){ A=A1; W=W1; cb=c1; C=C1; M=M1; }
    else { A=A2; W=W2; cb=c2; C=C2; M=M2; }
    int bm = blockIdx.x * 128;
    if (bm >= M) return;
    gemm_body(A, W, cb, C, G3, bm, blockIdx.y * 64);
}

__global__ __launch_bounds__(256) void gemm_atb(const float* __restrict__ A,
                                                const float* __restrict__ W,
                                                const float* __restrict__ bias,
                                                float* __restrict__ C, int N)
{
    gemm_body(A, W, bias, C, N, blockIdx.x * 128, blockIdx.y * 64);
}

// ---------------- 3) GRU recurrences: cluster-resident Whh, f32x2 FMAs ----------------
// Cluster of 4 CTAs; each CTA owns 64 hidden units (192 Whh rows in smem).
// 24 clusters: chains f (0..7), b (8..15), q (16..23); 16 batch per cluster.
// h broadcast buffer transposed to [k][batch] so batch-pairs load as 64-bit LDS.
#define GRU_CL_B 16
#define GRU_SMEM_FLOATS (192*257 + 2*256*GRU_CL_B)
#define GRU_SMEM_BYTES  (GRU_SMEM_FLOATS*4)

__global__ void __cluster_dims__(4,1,1) __launch_bounds__(256,1)
gru_kernel(const float* __restrict__ Whh_f, const float* __restrict__ Whh_b, const float* __restrict__ Whh_q,
           const float* __restrict__ bhh_f, const float* __restrict__ bhh_b, const float* __restrict__ bhh_q)
{
    extern __shared__ float sm[];
    float* Whs  = sm;                 // [192][257]
    float* hbuf = sm + 192*257;       // [2][256][16]

    int tid = threadIdx.x;
    unsigned rank = ctarank_();
    int cid   = blockIdx.x >> 2;
    int chain = cid >> 3;             // 0=f, 1=b, 2=q
    int b0    = (cid & 7) * GRU_CL_B;

    const float *Whh, *bhh, *gi;
    float* outp;
    int steps;
    if (chain == 0){ Whh = Whh_f; bhh = bhh_f; gi = g_gif; outp = g_outf; steps = S_;  }
    else if (chain == 1){ Whh = Whh_b; bhh = bhh_b; gi = g_gib; outp = g_outb; steps = S_;  }
    else { Whh = Whh_q; bhh = bhh_q; gi = g_giq; outp = g_q;    steps = TQ_; }

    // load this CTA's Whh slice (rows g*256 + rank*64 + jj), k along threads
    {
#pragma unroll 4
        for (int rr = 0; rr < 192; rr++){
            int g = rr >> 6, jj = rr & 63;
            Whs[rr*257 + tid] = Whh[((size_t)(g*256 + (int)rank*64 + jj))*256 + tid];
        }
        for (int i = tid; i < 2*256*GRU_CL_B; i += 256) hbuf[i] = 0.f;
    }
    cluster_sync_();

    int j  = tid & 63;
    int bg = tid >> 6;                // 0..3, each handles 4 batches
    int jglob = (int)rank*64 + j;
    float br = bhh[jglob], bz = bhh[256 + jglob], bn2 = bhh[512 + jglob];
    const float* wr = Whs +  j        *257;
    const float* wz = Whs + (64  + j) *257;
    const float* wn = Whs + (128 + j) *257;
    unsigned hbuf_base = smem_u32_(hbuf);
    float hp[4] = {0.f, 0.f, 0.f, 0.f};

    for (int step = 0; step < steps; step++){
        int cur = step & 1, nxt = cur ^ 1;
        int pos = (chain == 1) ? (S_ - 1 - step) : step;
        const float* hb = hbuf + cur*(256*GRU_CL_B);

        // prefetch input gates for this step (independent of h; hides L2 latency)
        float gr[4], gz[4], gn[4];
#pragma unroll
        for (int i = 0; i < 4; i++){
            const float* gir = gi + ((size_t)(b0 + bg*4 + i)*steps + pos)*G3 + jglob;
            gr[i] = gir[0]; gz[i] = gir[256]; gn[i] = gir[512];
        }

        // matvec: 3 gates x 4 batches over k=0..255, packed pairs
        ull ar0=0ull, ar1=0ull, az0=0ull, az1=0ull, an0=0ull, an1=0ull;
        const float* hcol = hb + bg*4;
#pragma unroll 8
        for (int k = 0; k < 256; k++){
            ull h01 = *(const ull*)(hcol + k*GRU_CL_B);
            ull h23 = *(const ull*)(hcol + k*GRU_CL_B + 2);
            ull wrp = dup2_(wr[k]);
            fma2_(ar0, wrp, h01); fma2_(ar1, wrp, h23);
            ull wzp = dup2_(wz[k]);
            fma2_(az0, wzp, h01); fma2_(az1, wzp, h23);
            ull wnp = dup2_(wn[k]);
            fma2_(an0, wnp, h01); fma2_(an1, wnp, h23);
        }
        float2 arA = unpack2_(ar0), arB = unpack2_(ar1);
        float2 azA = unpack2_(az0), azB = unpack2_(az1);
        float2 anA = unpack2_(an0), anB = unpack2_(an1);
        float arv[4] = {arA.x, arA.y, arB.x, arB.y};
        float azv[4] = {azA.x, azA.y, azB.x, azB.y};
        float anv[4] = {anA.x, anA.y, anB.x, anB.y};

#pragma unroll
        for (int i = 0; i < 4; i++){
            int bl = bg*4 + i;
            int bglob = b0 + bl;
            float rg = sigmoidf_(gr[i] + arv[i] + br);
            float zg = sigmoidf_(gz[i] + azv[i] + bz);
            float ng = tanhf(gn[i] + rg*(anv[i] + bn2));
            float hv = (1.f - zg)*ng + zg*hp[i];
            hp[i] = hv;
            if (chain == 2){ if (step == steps - 1) outp[(size_t)bglob*H_ + jglob] = hv; }
            else outp[((size_t)bglob*S_ + pos)*H_ + jglob] = hv;
            unsigned la = hbuf_base + (unsigned)((nxt*(256*GRU_CL_B) + jglob*GRU_CL_B + bl)*4);
            st_cluster_f32_(la, 0, hv);
            st_cluster_f32_(la, 1, hv);
            st_cluster_f32_(la, 2, hv);
            st_cluster_f32_(la, 3, hv);
        }
        cluster_sync_();
    }
}

// ---------------- 4) attention + read + tanh(q*read) ----------------
__global__ void attn_kernel(){
    int b = blockIdx.x, h = threadIdx.x;
    __shared__ float en[S_];
    __shared__ float red[8];
    float qh = g_q[(size_t)b*H_ + h];
    int lane = h & 31, wid = h >> 5;
    for (int s = 0; s < S_; s++){
        float f = g_outf[((size_t)b*S_ + s)*H_ + h] + g_outb[((size_t)b*S_ + s)*H_ + h];
        float p = f * qh;
#pragma unroll
        for (int o = 16; o; o >>= 1) p += __shfl_xor_sync(0xffffffffu, p, o);
        if (lane == 0) red[wid] = p;
        __syncthreads();
        if (h < 8){
            float t = red[h];
            t += __shfl_xor_sync(0xffu, t, 4);
            t += __shfl_xor_sync(0xffu, t, 2);
            t += __shfl_xor_sync(0xffu, t, 1);
            if (h == 0) en[s] = t;
        }
        __syncthreads();
    }
    float mx = -1e30f;
    for (int s = 0; s < S_; s++) mx = fmaxf(mx, en[s]);
    float sum = 0.f;
    for (int s = 0; s < S_; s++) sum += expf(en[s] - mx);
    float inv = 1.f / sum;
    float rd = 0.f;
    for (int s = 0; s < S_; s++){
        float a = expf(en[s] - mx) * inv;
        rd += a * (g_outf[((size_t)b*S_ + s)*H_ + h] + g_outb[((size_t)b*S_ + s)*H_ + h]);
    }
    g_af[(size_t)b*H_ + h] = tanhf(qh * rd);
}

// ---------------- launch ----------------
extern "C" void kernel_launch(void* const* d_in, const int* in_sizes, int n_in,
                              void* d_out, int out_size)
{
    const int*   contexts  = (const int*)  d_in[0];
    const int*   questions = (const int*)  d_in[1];
    const float* emb       = (const float*)d_in[2];
    const float* Wih_f     = (const float*)d_in[3];
    const float* Whh_f     = (const float*)d_in[4];
    const float* bih_f     = (const float*)d_in[5];
    const float* bhh_f     = (const float*)d_in[6];
    const float* Wih_b     = (const float*)d_in[7];
    const float* Whh_b     = (const float*)d_in[8];
    const float* bih_b     = (const float*)d_in[9];
    const float* bhh_b     = (const float*)d_in[10];
    const float* Wih_q     = (const float*)d_in[11];
    const float* Whh_q     = (const float*)d_in[12];
    const float* bih_q     = (const float*)d_in[13];
    const float* bhh_q     = (const float*)d_in[14];
    const float* Wo        = (const float*)d_in[15];
    const float* bo        = (const float*)d_in[16];
    float* out = (float*)d_out;

    float *p_ctx, *p_qemb, *p_gif, *p_gib, *p_giq, *p_af;
    cudaGetSymbolAddress((void**)&p_ctx,  g_ctx);
    cudaGetSymbolAddress((void**)&p_qemb, g_qemb);
    cudaGetSymbolAddress((void**)&p_gif,  g_gif);
    cudaGetSymbolAddress((void**)&p_gib,  g_gib);
    cudaGetSymbolAddress((void**)&p_giq,  g_giq);
    cudaGetSymbolAddress((void**)&p_af,   g_af);

    cudaFuncSetAttribute(gru_kernel, cudaFuncAttributeMaxDynamicSharedMemorySize, GRU_SMEM_BYTES);

    // 1) embeddings
    embed_pe_kernel<<<B_*S_, 256>>>(contexts, emb);
    qemb_kernel<<<B_*TQ_, 256>>>(questions, emb);

    // 2) all three input-gate GEMMs in one launch (z selects problem)
    gemm3_kernel<<<dim3(B_*S_/128, G3/64, 3), 256>>>(
        p_ctx,  Wih_f, bih_f, p_gif, B_*S_,
        p_ctx,  Wih_b, bih_b, p_gib, B_*S_,
        p_qemb, Wih_q, bih_q, p_giq, B_*TQ_);

    // 3) all three GRU chains concurrently (24 clusters x 4 CTAs)
    gru_kernel<<<96, 256, GRU_SMEM_BYTES>>>(Whh_f, Whh_b, Whh_q, bhh_f, bhh_b, bhh_q);

    // 4) attention + read + tanh
    attn_kernel<<<B_, 256>>>();

    // 5) vocab projection: out = af @ Wo^T + bo
    gemm_atb<<<dim3(1, (V_ + 63)/64), 256>>>(p_af, Wo, bo, out, V_);
}